// round 15
// baseline (speedup 1.0000x reference)
#include <cuda_runtime.h>
#include <cuda_bf16.h>
#include <cstdint>
#include <cstddef>

#define SEQ    2048
#define BATCH  128
#define INPUT  256
#define HIDDEN 512
#define MDIM   (SEQ * BATCH)          // 262144 GEMM rows

// ---------------------------------------------------------------------------
// Device scratch (no allocations allowed)
// ---------------------------------------------------------------------------
__device__ float g_xc[(size_t)SEQ * BATCH * HIDDEN];
__device__ float g_xa[(size_t)SEQ * BATCH * HIDDEN];
__device__ __nv_bfloat16 g_Ahi[(size_t)MDIM * INPUT];
__device__ __nv_bfloat16 g_Alo[(size_t)MDIM * INPUT];
__device__ __nv_bfloat16 g_Bhi[3 * HIDDEN * INPUT];
__device__ __nv_bfloat16 g_Blo[3 * HIDDEN * INPUT];

// ---------------------------------------------------------------------------
// PTX helpers (plain sm_75/80-level PTX; assembles for compute_103)
// ---------------------------------------------------------------------------
__device__ __forceinline__ uint32_t smem_to_u32(const void* p) {
    uint32_t a;
    asm("{ .reg .u64 t; cvta.to.shared.u64 t, %1; cvt.u32.u64 %0, t; }"
        : "=r"(a) : "l"(p));
    return a;
}
__device__ __forceinline__ void cp16(uint32_t dst, const void* src) {
    asm volatile("cp.async.cg.shared.global [%0], [%1], 16;"
                 :: "r"(dst), "l"(src));
}
#define CP_COMMIT() asm volatile("cp.async.commit_group;" ::: "memory")
#define CP_WAIT(n)  asm volatile("cp.async.wait_group %0;" :: "n"(n) : "memory")

__device__ __forceinline__ void ldsm_x4(uint32_t* r, uint32_t addr) {
    asm volatile("ldmatrix.sync.aligned.m8n8.x4.shared.b16 {%0,%1,%2,%3}, [%4];"
                 : "=r"(r[0]), "=r"(r[1]), "=r"(r[2]), "=r"(r[3]) : "r"(addr));
}
__device__ __forceinline__ void mma16816(float* c, const uint32_t* a,
                                         const uint32_t* b) {
    asm volatile(
        "mma.sync.aligned.m16n8k16.row.col.f32.bf16.bf16.f32 "
        "{%0,%1,%2,%3}, {%4,%5,%6,%7}, {%8,%9}, {%0,%1,%2,%3};"
        : "+f"(c[0]), "+f"(c[1]), "+f"(c[2]), "+f"(c[3])
        : "r"(a[0]), "r"(a[1]), "r"(a[2]), "r"(a[3]), "r"(b[0]), "r"(b[1]));
}
__device__ __forceinline__ uint32_t sw128(uint32_t off) {
    return off ^ ((off >> 3) & 0x70);
}
__device__ __forceinline__ float tanh_ap(float x) {
    float y;
    asm("tanh.approx.f32 %0, %1;" : "=f"(y) : "f"(x));
    return y;
}

// ---------------------------------------------------------------------------
// Pre-pass: split fp32 -> bf16 hi/lo
// ---------------------------------------------------------------------------
__global__ void splitA(const float* __restrict__ x) {
    const size_t base = ((size_t)blockIdx.x * blockDim.x + threadIdx.x) * 8;
    float4 a = *(const float4*)(x + base);
    float4 b = *(const float4*)(x + base + 4);
    float f[8] = {a.x, a.y, a.z, a.w, b.x, b.y, b.z, b.w};
    union { __nv_bfloat16 h[8]; uint4 u; } H, L;
#pragma unroll
    for (int k = 0; k < 8; k++) {
        H.h[k] = __float2bfloat16_rn(f[k]);
        L.h[k] = __float2bfloat16_rn(f[k] - __bfloat162float(H.h[k]));
    }
    *(uint4*)(g_Ahi + base) = H.u;
    *(uint4*)(g_Alo + base) = L.u;
}
__global__ void splitB3(const float* __restrict__ Uc,
                        const float* __restrict__ Ua,
                        const float* __restrict__ Uh) {
    const int proj = blockIdx.y;
    const float* u = (proj == 0) ? Uc : (proj == 1) ? Ua : Uh;
    const size_t base = ((size_t)blockIdx.x * blockDim.x + threadIdx.x) * 8;
    const size_t off = (size_t)proj * HIDDEN * INPUT;
    float4 a = *(const float4*)(u + base);
    float4 b = *(const float4*)(u + base + 4);
    float f[8] = {a.x, a.y, a.z, a.w, b.x, b.y, b.z, b.w};
    union { __nv_bfloat16 h[8]; uint4 u4; } H, L;
#pragma unroll
    for (int k = 0; k < 8; k++) {
        H.h[k] = __float2bfloat16_rn(f[k]);
        L.h[k] = __float2bfloat16_rn(f[k] - __bfloat162float(H.h[k]));
    }
    *(uint4*)(g_Bhi + off + base) = H.u4;
    *(uint4*)(g_Blo + off + base) = L.u4;
}

// ---------------------------------------------------------------------------
// Persistent-B GEMM, WIDE warp tiles (64x64): CTA tile 256(M) x 128(N),
// grid (12, 128), 256 threads, 8 warps as 4(M-quarter) x 2(N-half).
// LDSM bytes per MMA reduced 33% vs 32x64 tiles (crossbar relief).
// B hi/lo resident (128 KB, SW128, 4 kc64 mats each). A streamed in K=32
// chunks: 256 rows packed into 128 smem rows x 128 B (row g -> smem row
// g&127, byte-col (g>>7)*64), hi+lo = 32 KB/stage, 3 stages, copy lead 2,
// one __syncthreads per chunk. Terms: Ah*Bh + Al*Bh + Ah*Bl, fp32 accum.
// ---------------------------------------------------------------------------
#define MATB     16384                 // B mat: 128 rows x 128 B
#define ACH      32768                 // A chunk stage: hi 16KB + lo 16KB
#define SM_B     0                     // 8 mats: (kc64*2+hl)*MATB
#define SM_A     (8 * MATB)            // 131072: 3 stages
#define SM_BIAS  (SM_A + 3 * ACH)      // 229376
#define SMEM_TOT (SM_BIAS + 512)       // 229888 bytes
#define TILES    8
#define NQ       (TILES * 8)           // 64 K=32 chunks

__global__ __launch_bounds__(256, 1)
void brc_gemm_pb(const float* __restrict__ bc, const float* __restrict__ ba,
                 float* __restrict__ xh_out) {
    extern __shared__ __align__(1024) char smem[];
    const uint32_t sb = smem_to_u32(smem);
    const int tid = threadIdx.x;
    const int wid = tid >> 5;
    const int lid = tid & 31;

    const int colblk = blockIdx.x;     // 0..11
    const int proj   = colblk >> 2;
    const int nb     = colblk & 3;
    const int yb     = blockIdx.y;     // 0..127

    float* __restrict__ C = (proj == 0) ? g_xc : (proj == 1) ? g_xa : xh_out;

    // warp layout: 4(M quarters of 64) x 2(N halves of 64)
    const int wm = wid & 3;
    const int wn = wid >> 2;

    // bias -> smem (zero for proj 2)
    if (tid < 128) {
        float bv = 0.0f;
        if (proj == 0) bv = bc[nb * 128 + tid];
        else if (proj == 1) bv = ba[nb * 128 + tid];
        ((float*)(smem + SM_BIAS))[tid] = bv;
    }

    // ---- B preload: 8 mats (4 kc64 x hi/lo), 32 cp.async per thread ----
    {
        const __nv_bfloat16* Bh = g_Bhi + (size_t)proj * HIDDEN * INPUT
                                        + (size_t)(nb * 128) * INPUT;
        const __nv_bfloat16* Bl = g_Blo + (size_t)proj * HIDDEN * INPUT
                                        + (size_t)(nb * 128) * INPUT;
#pragma unroll
        for (int i = 0; i < 32; i++) {
            const int kcmat = i >> 2;              // 0..7
            const int kc = kcmat >> 1, hl = kcmat & 1;
            const int within = ((i & 3) << 8) + tid;   // 0..1023
            const int r = within >> 3, s = within & 7;
            const __nv_bfloat16* g = ((hl == 0) ? Bh : Bl)
                                     + (size_t)r * INPUT + kc * 64 + s * 8;
            cp16(sb + (uint32_t)(SM_B + kcmat * MATB + sw128(r * 128 + s * 16)), g);
        }
        CP_COMMIT();
    }

    // A chunk copy: q (0..63): tile t = q>>3, kc32 = q&7; stage = q%3.
    // 256 global rows x 32 k (hi+lo) = 32KB -> 8 cp16 per thread.
    auto copy_A = [&](int q) {
        const int t = q >> 3, kc = q & 7;
        const size_t mrow = (size_t)(yb * 8 + t) * 256;
        const uint32_t stage = sb + (uint32_t)(SM_A + (q % 3) * ACH);
#pragma unroll
        for (int i = 0; i < 8; i++) {
            const int hl = i >> 2;
            const int within = ((i & 3) << 8) + tid;   // 0..1023
            const int gr = within >> 2, s = within & 3;
            const __nv_bfloat16* g = ((hl == 0) ? g_Ahi : g_Alo)
                + (mrow + gr) * INPUT + kc * 32 + s * 8;
            const uint32_t off = (uint32_t)((gr & 127) * 128
                                            + (gr >> 7) * 64 + s * 16);
            cp16(stage + (uint32_t)(hl * 16384 + sw128(off)), g);
        }
        CP_COMMIT();
    };
    copy_A(0);
    copy_A(1);

    // ldmatrix lane address components
    const int aRowM = (wm & 1) * 64 + (lid & 15);    // smem row (+ mt*16)
    const int aHalf = (wm >> 1) * 64;                // byte-col half (M>=128)
    const int aColB = ((lid >> 4) << 4);             // byte col 0/16
    const int bRow  = wn * 64 + (lid & 7) + ((lid >> 4) << 3);  // + pr*16
    const int bColB = (((lid >> 3) & 1) << 4);       // byte col 0/16

    float cfr[4][8][4];                              // 128 fp32 accumulators
    const float* sBias = (const float*)(smem + SM_BIAS);

    for (int q = 0; q < NQ; q++) {
        const int kc = q & 7;
        if (kc == 0) {
#pragma unroll
            for (int mt = 0; mt < 4; mt++)
#pragma unroll
                for (int nt = 0; nt < 8; nt++)
#pragma unroll
                    for (int p = 0; p < 4; p++) cfr[mt][nt][p] = 0.0f;
        }
        CP_WAIT(1);
        __syncthreads();            // also protects stage (q+2)%3 reuse
        if (q + 2 < NQ) copy_A(q + 2);

        const uint32_t abuf = sb + (uint32_t)(SM_A + (q % 3) * ACH);
        const uint32_t bbuf = sb + (uint32_t)(SM_B + (kc >> 1) * 2 * MATB);
        const int binner = (kc & 1) * 64;            // 64B half of the k64 mat

#pragma unroll
        for (int k16 = 0; k16 < 2; k16++) {
            const int akcol = aHalf + ((k16 << 5) & 63) + ((k16 >> 1) * 0);
            const int acol = aHalf + k16 * 32;       // A byte col base
            const int bkcol = binner + k16 * 32;     // B byte col
            uint32_t ah[4][4], al[4][4], bb[8][2];
            (void)akcol;
#pragma unroll
            for (int mt = 0; mt < 4; mt++)           // A hi: 4 quarters of 16r
                ldsm_x4(ah[mt], abuf + sw128((aRowM + mt * 16) * 128
                                             + acol + aColB));
#pragma unroll
            for (int pr = 0; pr < 4; pr++)           // B hi
                ldsm_x4(&bb[pr * 2][0], bbuf + sw128((bRow + pr * 16) * 128
                                                     + bkcol + bColB));
#pragma unroll
            for (int mt = 0; mt < 4; mt++)           // T1: Ah x Bh
#pragma unroll
                for (int nt = 0; nt < 8; nt++)
                    mma16816(cfr[mt][nt], ah[mt], bb[nt]);
#pragma unroll
            for (int mt = 0; mt < 4; mt++)           // A lo
                ldsm_x4(al[mt], abuf + (uint32_t)16384
                                + sw128((aRowM + mt * 16) * 128
                                        + acol + aColB));
#pragma unroll
            for (int mt = 0; mt < 4; mt++)           // T3: Al x Bh
#pragma unroll
                for (int nt = 0; nt < 8; nt++)
                    mma16816(cfr[mt][nt], al[mt], bb[nt]);
#pragma unroll
            for (int pr = 0; pr < 4; pr++)           // B lo (reuse bb)
                ldsm_x4(&bb[pr * 2][0], bbuf + (uint32_t)MATB
                                        + sw128((bRow + pr * 16) * 128
                                                + bkcol + bColB));
#pragma unroll
            for (int mt = 0; mt < 4; mt++)           // T2: Ah x Bl
#pragma unroll
                for (int nt = 0; nt < 8; nt++)
                    mma16816(cfr[mt][nt], ah[mt], bb[nt]);
        }

        if (kc == 7) {      // fp32 epilogue for tile t
            const int t = q >> 3;
            // warp covers global rows (wm>>1)*128 + (wm&1)*64 + mt*16 + ...
            const int mbase = (yb * 8 + t) * 256 + (wm >> 1) * 128
                            + (wm & 1) * 64 + (lid >> 2);
            const int t2 = (lid & 3) * 2;
#pragma unroll
            for (int mt = 0; mt < 4; mt++) {
                const size_t m0 = (size_t)(mbase + mt * 16);
#pragma unroll
                for (int nt = 0; nt < 8; nt++) {
                    const int ncol = wn * 64 + nt * 8 + t2;
                    const float b0 = sBias[ncol], b1 = sBias[ncol + 1];
                    float* p0 = C + m0 * HIDDEN + nb * 128 + ncol;
                    *(float2*)p0 = make_float2(cfr[mt][nt][0] + b0,
                                               cfr[mt][nt][1] + b1);
                    *(float2*)(p0 + 8 * HIDDEN) = make_float2(
                        cfr[mt][nt][2] + b0, cfr[mt][nt][3] + b1);
                }
            }
        }
    }
}

// ---------------------------------------------------------------------------
// Phase 2: scan: float2 lanes, ALL transcendentals via MUFU.TANH
// (sigmoid(x) = 0.5 + 0.5*tanh(x/2); MUFU 4 -> 3 per element-step), PF=8.
// ---------------------------------------------------------------------------
#define PF 8
__global__ __launch_bounds__(128)
void brc_scan(float* __restrict__ out, const float* __restrict__ h0,
              const float* __restrict__ w_c, const float* __restrict__ w_a,
              float* __restrict__ hn) {
    const int gt = blockIdx.x * 128 + threadIdx.x;      // 0..32767
    const int e0 = gt * 2;
    const int j = e0 & (HIDDEN - 1);
    const float2 wc = *(const float2*)(w_c + j);
    const float2 wa = *(const float2*)(w_a + j);
    float2 h = *(const float2*)(h0 + e0);
    const int STRIDE = BATCH * HIDDEN;

    const float2* XC = (const float2*)g_xc;
    const float2* XA = (const float2*)g_xa;
    float2* OUT = (float2*)out;
    const int S2 = STRIDE / 2;

    float2 xcb[PF], xab[PF], xhb[PF];
#pragma unroll
    for (int p = 0; p < PF; p++) {
        const size_t i = (size_t)p * S2 + gt;
        xcb[p] = __ldcs(XC + i);
        xab[p] = __ldcs(XA + i);
        xhb[p] = __ldcs(OUT + i);
    }

    size_t idx = (size_t)gt;
#pragma unroll 8
    for (int t = 0; t < SEQ; ++t, idx += S2) {
        const int sl = t & (PF - 1);
        const float2 xc_c = xcb[sl], xa_c = xab[sl], xh_c = xhb[sl];
        if (t + PF < SEQ) {
            const size_t nxt = idx + (size_t)PF * S2;
            xcb[sl] = __ldcs(XC + nxt);
            xab[sl] = __ldcs(XA + nxt);
            xhb[sl] = __ldcs(OUT + nxt);
        }
        {
            const float c  = fmaf(0.5f, tanh_ap(0.5f * (xc_c.x + wc.x * h.x)), 0.5f);
            const float a  = 1.0f + tanh_ap(xa_c.x + wa.x * h.x);
            const float t3 = tanh_ap(xh_c.x + a * h.x);
            h.x = fmaf(c, h.x - t3, t3);
        }
        {
            const float c  = fmaf(0.5f, tanh_ap(0.5f * (xc_c.y + wc.y * h.y)), 0.5f);
            const float a  = 1.0f + tanh_ap(xa_c.y + wa.y * h.y);
            const float t3 = tanh_ap(xh_c.y + a * h.y);
            h.y = fmaf(c, h.y - t3, t3);
        }
        __stcs(OUT + idx, h);
    }
    if (hn) *(float2*)(hn + e0) = h;
}

// ---------------------------------------------------------------------------
extern "C" void kernel_launch(void* const* d_in, const int* in_sizes, int n_in,
                              void* d_out, int out_size) {
    const float* x  = (const float*)d_in[0];
    const float* h0 = (const float*)d_in[1];
    const float* Uc = (const float*)d_in[2];
    const float* wc = (const float*)d_in[3];
    const float* bc = (const float*)d_in[4];
    const float* Ua = (const float*)d_in[5];
    const float* wa = (const float*)d_in[6];
    const float* ba = (const float*)d_in[7];
    const float* Uh = (const float*)d_in[8];

    float* out = (float*)d_out;
    const size_t out_elems = (size_t)SEQ * BATCH * HIDDEN;
    float* hn = ((size_t)out_size >= out_elems + (size_t)BATCH * HIDDEN)
                    ? (out + out_elems) : nullptr;

    // Pre-pass: fp32 -> bf16 hi/lo splits
    splitA<<<(MDIM * INPUT / 8) / 256, 256>>>(x);
    dim3 gb(HIDDEN * INPUT / 8 / 256, 3);
    splitB3<<<gb, 256>>>(Uc, Ua, Uh);

    // Phase 1: persistent-B GEMM, 64x64 warp tiles (crossbar relief)
    cudaFuncSetAttribute(brc_gemm_pb,
                         cudaFuncAttributeMaxDynamicSharedMemorySize, SMEM_TOT);
    dim3 grid(12, 128);
    brc_gemm_pb<<<grid, 256, SMEM_TOT>>>(bc, ba, out);

    // Phase 2: recurrent scan, float2 lanes, in place over xh
    brc_scan<<<(BATCH * HIDDEN / 2) / 128, 128>>>(out, h0, wc, wa, hn);
}

// round 16
// speedup vs baseline: 1.0945x; 1.0945x over previous
#include <cuda_runtime.h>
#include <cuda_bf16.h>
#include <cstdint>
#include <cstddef>

#define SEQ    2048
#define BATCH  128
#define INPUT  256
#define HIDDEN 512
#define MDIM   (SEQ * BATCH)          // 262144 GEMM rows

// ---------------------------------------------------------------------------
// Device scratch (no allocations allowed)
// ---------------------------------------------------------------------------
__device__ float g_xc[(size_t)SEQ * BATCH * HIDDEN];
__device__ float g_xa[(size_t)SEQ * BATCH * HIDDEN];
__device__ __nv_bfloat16 g_Ahi[(size_t)MDIM * INPUT];
__device__ __nv_bfloat16 g_Alo[(size_t)MDIM * INPUT];
__device__ __nv_bfloat16 g_Bhi[3 * HIDDEN * INPUT];
__device__ __nv_bfloat16 g_Blo[3 * HIDDEN * INPUT];

// ---------------------------------------------------------------------------
// PTX helpers (plain sm_75/80-level PTX; assembles for compute_103)
// ---------------------------------------------------------------------------
__device__ __forceinline__ uint32_t smem_to_u32(const void* p) {
    uint32_t a;
    asm("{ .reg .u64 t; cvta.to.shared.u64 t, %1; cvt.u32.u64 %0, t; }"
        : "=r"(a) : "l"(p));
    return a;
}
__device__ __forceinline__ void cp16(uint32_t dst, const void* src) {
    asm volatile("cp.async.cg.shared.global [%0], [%1], 16;"
                 :: "r"(dst), "l"(src));
}
#define CP_COMMIT() asm volatile("cp.async.commit_group;" ::: "memory")
#define CP_WAIT(n)  asm volatile("cp.async.wait_group %0;" :: "n"(n) : "memory")

__device__ __forceinline__ void ldsm_x4(uint32_t* r, uint32_t addr) {
    asm volatile("ldmatrix.sync.aligned.m8n8.x4.shared.b16 {%0,%1,%2,%3}, [%4];"
                 : "=r"(r[0]), "=r"(r[1]), "=r"(r[2]), "=r"(r[3]) : "r"(addr));
}
__device__ __forceinline__ void mma16816(float* c, const uint32_t* a,
                                         const uint32_t* b) {
    asm volatile(
        "mma.sync.aligned.m16n8k16.row.col.f32.bf16.bf16.f32 "
        "{%0,%1,%2,%3}, {%4,%5,%6,%7}, {%8,%9}, {%0,%1,%2,%3};"
        : "+f"(c[0]), "+f"(c[1]), "+f"(c[2]), "+f"(c[3])
        : "r"(a[0]), "r"(a[1]), "r"(a[2]), "r"(a[3]), "r"(b[0]), "r"(b[1]));
}
__device__ __forceinline__ uint32_t sw128(uint32_t off) {
    return off ^ ((off >> 3) & 0x70);
}
__device__ __forceinline__ float tanh_ap(float x) {
    float y;
    asm("tanh.approx.f32 %0, %1;" : "=f"(y) : "f"(x));
    return y;
}

// ---------------------------------------------------------------------------
// Pre-pass: split fp32 -> bf16 hi/lo
// ---------------------------------------------------------------------------
__global__ void splitA(const float* __restrict__ x) {
    const size_t base = ((size_t)blockIdx.x * blockDim.x + threadIdx.x) * 8;
    float4 a = *(const float4*)(x + base);
    float4 b = *(const float4*)(x + base + 4);
    float f[8] = {a.x, a.y, a.z, a.w, b.x, b.y, b.z, b.w};
    union { __nv_bfloat16 h[8]; uint4 u; } H, L;
#pragma unroll
    for (int k = 0; k < 8; k++) {
        H.h[k] = __float2bfloat16_rn(f[k]);
        L.h[k] = __float2bfloat16_rn(f[k] - __bfloat162float(H.h[k]));
    }
    *(uint4*)(g_Ahi + base) = H.u;
    *(uint4*)(g_Alo + base) = L.u;
}
__global__ void splitB3(const float* __restrict__ Uc,
                        const float* __restrict__ Ua,
                        const float* __restrict__ Uh) {
    const int proj = blockIdx.y;
    const float* u = (proj == 0) ? Uc : (proj == 1) ? Ua : Uh;
    const size_t base = ((size_t)blockIdx.x * blockDim.x + threadIdx.x) * 8;
    const size_t off = (size_t)proj * HIDDEN * INPUT;
    float4 a = *(const float4*)(u + base);
    float4 b = *(const float4*)(u + base + 4);
    float f[8] = {a.x, a.y, a.z, a.w, b.x, b.y, b.z, b.w};
    union { __nv_bfloat16 h[8]; uint4 u4; } H, L;
#pragma unroll
    for (int k = 0; k < 8; k++) {
        H.h[k] = __float2bfloat16_rn(f[k]);
        L.h[k] = __float2bfloat16_rn(f[k] - __bfloat162float(H.h[k]));
    }
    *(uint4*)(g_Bhi + off + base) = H.u4;
    *(uint4*)(g_Blo + off + base) = L.u4;
}

// ---------------------------------------------------------------------------
// Persistent-B mma.sync GEMM (R11 proven shape). grid = (12, 256), block 256.
// B hi/lo resident (128 KB, SW128); 8 M-tiles per CTA; A streamed in K=64
// chunks, THREE 32 KB stages, copy lead 2, one __syncthreads per chunk.
// 3 split terms: Ah*Bh + Al*Bh + Ah*Bl. fp32 accumulate + bias epilogue.
// ---------------------------------------------------------------------------
#define MATB     16384                 // 128 x 128 B
#define SM_B     0                     // 8 mats: (kc*2+hl)*MATB, kc 0..3
#define SM_A     (8 * MATB)            // 3 stages x {hi, lo}
#define ASTAGE   (2 * MATB)
#define SM_BIAS  (SM_A + 3 * ASTAGE)   // 229376
#define SMEM_TOT (SM_BIAS + 512)       // 229888 bytes
#define TILES    8
#define NQ       (TILES * 4)           // 32 K-chunks

__global__ __launch_bounds__(256, 1)
void brc_gemm_pb(const float* __restrict__ bc, const float* __restrict__ ba,
                 float* __restrict__ xh_out) {
    extern __shared__ __align__(1024) char smem[];
    const uint32_t sb = smem_to_u32(smem);
    const int tid = threadIdx.x;
    const int wid = tid >> 5;
    const int lid = tid & 31;

    const int colblk = blockIdx.x;     // 0..11
    const int proj   = colblk >> 2;
    const int nb     = colblk & 3;
    const int yb     = blockIdx.y;     // 0..255

    float* __restrict__ C = (proj == 0) ? g_xc : (proj == 1) ? g_xa : xh_out;

    // bias -> smem (zero for proj 2)
    if (tid < 128) {
        float bv = 0.0f;
        if (proj == 0) bv = bc[nb * 128 + tid];
        else if (proj == 1) bv = ba[nb * 128 + tid];
        ((float*)(smem + SM_BIAS))[tid] = bv;
    }

    // ---- B preload: 8 mats (4 kc x hi/lo), 32 cp.async per thread ----
    {
        const __nv_bfloat16* Bh = g_Bhi + (size_t)proj * HIDDEN * INPUT
                                        + (size_t)(nb * 128) * INPUT;
        const __nv_bfloat16* Bl = g_Blo + (size_t)proj * HIDDEN * INPUT
                                        + (size_t)(nb * 128) * INPUT;
#pragma unroll
        for (int i = 0; i < 32; i++) {
            const int kcmat = i >> 2;              // 0..7
            const int kc = kcmat >> 1, hl = kcmat & 1;
            const int within = ((i & 3) << 8) + tid;   // 0..1023
            const int r = within >> 3, s = within & 7;
            const __nv_bfloat16* g = ((hl == 0) ? Bh : Bl)
                                     + (size_t)r * INPUT + kc * 64 + s * 8;
            cp16(sb + (uint32_t)(SM_B + kcmat * MATB + sw128(r * 128 + s * 16)), g);
        }
        CP_COMMIT();
    }

    // A chunk copy: q (0..31): tile t = q>>2, kc = q&3; stage = q%3
    auto copy_A = [&](int q) {
        const int t = q >> 2, kc = q & 3;
        const size_t mrow = (size_t)(yb * 8 + t) * 128;
        const uint32_t stage = sb + (uint32_t)(SM_A + (q % 3) * ASTAGE);
#pragma unroll
        for (int i = 0; i < 8; i++) {
            const int hl = i >> 2;
            const int within = ((i & 3) << 8) + tid;
            const int r = within >> 3, s = within & 7;
            const __nv_bfloat16* g = ((hl == 0) ? g_Ahi : g_Alo)
                + (mrow + r) * INPUT + kc * 64 + s * 8;
            cp16(stage + (uint32_t)(hl * MATB + sw128(r * 128 + s * 16)), g);
        }
        CP_COMMIT();
    };
    copy_A(0);
    copy_A(1);

    // warp layout: 4(M) x 2(N); warp tile 32 x 64
    const int wm = wid & 3;
    const int wn = wid >> 2;
    const int aRow  = wm * 32 + (lid & 15);          // + mt*16
    const int aColB = ((lid >> 4) << 4);             // byte col 0/16
    const int bRow  = wn * 64 + (lid & 7) + ((lid >> 4) << 3);  // + pr*16
    const int bColB = (((lid >> 3) & 1) << 4);       // byte col 0/16

    float cfr[2][8][4];
    const float* sBias = (const float*)(smem + SM_BIAS);

    for (int q = 0; q < NQ; q++) {
        const int kc = q & 3;
        if (kc == 0) {
#pragma unroll
            for (int mt = 0; mt < 2; mt++)
#pragma unroll
                for (int nt = 0; nt < 8; nt++)
#pragma unroll
                    for (int p = 0; p < 4; p++) cfr[mt][nt][p] = 0.0f;
        }
        CP_WAIT(1);
        __syncthreads();            // also protects stage (q+2)%3 reuse
        if (q + 2 < NQ) copy_A(q + 2);

        const uint32_t abuf = sb + (uint32_t)(SM_A + (q % 3) * ASTAGE);
        const uint32_t bbuf = sb + (uint32_t)(SM_B + kc * 2 * MATB);
#pragma unroll
        for (int k16 = 0; k16 < 4; k16++) {
            const int kcolb = k16 * 32;             // byte col of k16 block
            uint32_t ah[2][4], al[2][4], bb[8][2];
#pragma unroll
            for (int mt = 0; mt < 2; mt++)
                ldsm_x4(ah[mt], abuf + sw128((aRow + mt * 16) * 128
                                             + kcolb + aColB));
#pragma unroll
            for (int pr = 0; pr < 4; pr++)          // B hi
                ldsm_x4(&bb[pr * 2][0], bbuf + sw128((bRow + pr * 16) * 128
                                                     + kcolb + bColB));
#pragma unroll
            for (int mt = 0; mt < 2; mt++)          // T1: Ah x Bh
#pragma unroll
                for (int nt = 0; nt < 8; nt++)
                    mma16816(cfr[mt][nt], ah[mt], bb[nt]);
#pragma unroll
            for (int mt = 0; mt < 2; mt++)          // A lo
                ldsm_x4(al[mt], abuf + (uint32_t)MATB
                                + sw128((aRow + mt * 16) * 128
                                        + kcolb + aColB));
#pragma unroll
            for (int mt = 0; mt < 2; mt++)          // T3: Al x Bh
#pragma unroll
                for (int nt = 0; nt < 8; nt++)
                    mma16816(cfr[mt][nt], al[mt], bb[nt]);
#pragma unroll
            for (int pr = 0; pr < 4; pr++)          // B lo (reuse bb)
                ldsm_x4(&bb[pr * 2][0], bbuf + (uint32_t)MATB
                                        + sw128((bRow + pr * 16) * 128
                                                + kcolb + bColB));
#pragma unroll
            for (int mt = 0; mt < 2; mt++)          // T2: Ah x Bl
#pragma unroll
                for (int nt = 0; nt < 8; nt++)
                    mma16816(cfr[mt][nt], ah[mt], bb[nt]);
        }

        if (kc == 3) {      // fp32 epilogue for tile t
            const int t = q >> 2;
            const int mbase = (yb * 8 + t) * 128 + wm * 32 + (lid >> 2);
            const int t2 = (lid & 3) * 2;
#pragma unroll
            for (int mt = 0; mt < 2; mt++) {
                const size_t m0 = (size_t)(mbase + mt * 16);
#pragma unroll
                for (int nt = 0; nt < 8; nt++) {
                    const int ncol = wn * 64 + nt * 8 + t2;
                    const float b0 = sBias[ncol], b1 = sBias[ncol + 1];
                    float* p0 = C + m0 * HIDDEN + nb * 128 + ncol;
                    *(float2*)p0 = make_float2(cfr[mt][nt][0] + b0,
                                               cfr[mt][nt][1] + b1);
                    *(float2*)(p0 + 8 * HIDDEN) = make_float2(
                        cfr[mt][nt][2] + b0, cfr[mt][nt][3] + b1);
                }
            }
        }
    }
}

// ---------------------------------------------------------------------------
// Phase 2: scan (R15 proven): float2 lanes, ALL transcendentals via
// MUFU.TANH (sigmoid(x) = 0.5 + 0.5*tanh(x/2); 3 MUFU per element-step),
// PF=8, streaming loads/stores.
// ---------------------------------------------------------------------------
#define PF 8
__global__ __launch_bounds__(128)
void brc_scan(float* __restrict__ out, const float* __restrict__ h0,
              const float* __restrict__ w_c, const float* __restrict__ w_a,
              float* __restrict__ hn) {
    const int gt = blockIdx.x * 128 + threadIdx.x;      // 0..32767
    const int e0 = gt * 2;
    const int j = e0 & (HIDDEN - 1);
    const float2 wc = *(const float2*)(w_c + j);
    const float2 wa = *(const float2*)(w_a + j);
    float2 h = *(const float2*)(h0 + e0);
    const int STRIDE = BATCH * HIDDEN;

    const float2* XC = (const float2*)g_xc;
    const float2* XA = (const float2*)g_xa;
    float2* OUT = (float2*)out;
    const int S2 = STRIDE / 2;

    float2 xcb[PF], xab[PF], xhb[PF];
#pragma unroll
    for (int p = 0; p < PF; p++) {
        const size_t i = (size_t)p * S2 + gt;
        xcb[p] = __ldcs(XC + i);
        xab[p] = __ldcs(XA + i);
        xhb[p] = __ldcs(OUT + i);
    }

    size_t idx = (size_t)gt;
#pragma unroll 8
    for (int t = 0; t < SEQ; ++t, idx += S2) {
        const int sl = t & (PF - 1);
        const float2 xc_c = xcb[sl], xa_c = xab[sl], xh_c = xhb[sl];
        if (t + PF < SEQ) {
            const size_t nxt = idx + (size_t)PF * S2;
            xcb[sl] = __ldcs(XC + nxt);
            xab[sl] = __ldcs(XA + nxt);
            xhb[sl] = __ldcs(OUT + nxt);
        }
        {
            const float c  = fmaf(0.5f, tanh_ap(0.5f * (xc_c.x + wc.x * h.x)), 0.5f);
            const float a  = 1.0f + tanh_ap(xa_c.x + wa.x * h.x);
            const float t3 = tanh_ap(xh_c.x + a * h.x);
            h.x = fmaf(c, h.x - t3, t3);
        }
        {
            const float c  = fmaf(0.5f, tanh_ap(0.5f * (xc_c.y + wc.y * h.y)), 0.5f);
            const float a  = 1.0f + tanh_ap(xa_c.y + wa.y * h.y);
            const float t3 = tanh_ap(xh_c.y + a * h.y);
            h.y = fmaf(c, h.y - t3, t3);
        }
        __stcs(OUT + idx, h);
    }
    if (hn) *(float2*)(hn + e0) = h;
}

// ---------------------------------------------------------------------------
extern "C" void kernel_launch(void* const* d_in, const int* in_sizes, int n_in,
                              void* d_out, int out_size) {
    const float* x  = (const float*)d_in[0];
    const float* h0 = (const float*)d_in[1];
    const float* Uc = (const float*)d_in[2];
    const float* wc = (const float*)d_in[3];
    const float* bc = (const float*)d_in[4];
    const float* Ua = (const float*)d_in[5];
    const float* wa = (const float*)d_in[6];
    const float* ba = (const float*)d_in[7];
    const float* Uh = (const float*)d_in[8];

    float* out = (float*)d_out;
    const size_t out_elems = (size_t)SEQ * BATCH * HIDDEN;
    float* hn = ((size_t)out_size >= out_elems + (size_t)BATCH * HIDDEN)
                    ? (out + out_elems) : nullptr;

    // Pre-pass: fp32 -> bf16 hi/lo splits
    splitA<<<(MDIM * INPUT / 8) / 256, 256>>>(x);
    dim3 gb(HIDDEN * INPUT / 8 / 256, 3);
    splitB3<<<gb, 256>>>(Uc, Ua, Uh);

    // Phase 1: persistent-B mma.sync GEMMs (R11 shape)
    cudaFuncSetAttribute(brc_gemm_pb,
                         cudaFuncAttributeMaxDynamicSharedMemorySize, SMEM_TOT);
    dim3 grid(12, 256);
    brc_gemm_pb<<<grid, 256, SMEM_TOT>>>(bc, ba, out);

    // Phase 2: recurrent scan, float2 lanes, in place over xh
    brc_scan<<<(BATCH * HIDDEN / 2) / 128, 128>>>(out, h0, wc, wa, hn);
}